// round 4
// baseline (speedup 1.0000x reference)
#include <cuda_runtime.h>
#include <cuda_bf16.h>

#define FULL_MASK 0xFFFFFFFFu

// 4 quarter-row segments per row -> 1024 blocks of 256 threads.
// 4 CTAs co-resident per SM; per-SM work quantum = quarter row => tail ~1.7%.
#define SEGS  4
#define BROWS 256
#define NBLK  (BROWS * SEGS)

// Cross-segment parity handoff. bit1 = ready, bit0 = segment flip parity.
__device__ int g_flags[NBLK];

__global__ void init_flags_kernel() { g_flags[threadIdx.x] = 0; }

static __device__ __forceinline__ float fast_sqrt(float x) {
    float y;
    asm("sqrt.approx.f32 %0, %1;" : "=f"(y) : "f"(x));
    return y;
}

static __device__ __forceinline__ float apply_sign(float a, unsigned neg) {
    return __uint_as_float(__float_as_uint(a) ^ (neg << 31));
}

static __device__ __forceinline__ void publish_flag(int* p, int v) {
    asm volatile("st.global.release.gpu.b32 [%0], %1;" :: "l"(p), "r"(v) : "memory");
}

static __device__ __forceinline__ int read_flag(const int* p) {
    int v;
    asm volatile("ld.global.acquire.gpu.b32 %0, [%1];" : "=r"(v) : "l"(p) : "memory");
    return v;
}

// Pass 2 specialized on the row's 16B misalignment O = (row*131073) & 3.
// Each lane loads two aligned quads covering e[t-O .. t-O+7] and statically
// selects e[t..t+4]. 32-iteration deep loop preserves load front-batching.
template <int O>
static __device__ __forceinline__ void pass2(const float4* __restrict__ e4all,
                                             int qbase, int warpBase, int lane,
                                             uint4 bits, unsigned pfx, unsigned baseAll,
                                             float4* __restrict__ out4)
{
    #pragma unroll
    for (int i = 0; i < 32; i++) {
        const int t = warpBase + i * 128 + lane * 4;
        const int q = qbase + (t >> 2);
        float4 a = e4all[q];
        float4 b = e4all[q + 1];

        float e0, e1, e2, e3, e4;
        if (O == 0)      { e0 = a.x; e1 = a.y; e2 = a.z; e3 = a.w; e4 = b.x; }
        else if (O == 1) { e0 = a.y; e1 = a.z; e2 = a.w; e3 = b.x; e4 = b.y; }
        else if (O == 2) { e0 = a.z; e1 = a.w; e2 = b.x; e3 = b.y; e4 = b.z; }
        else             { e0 = a.w; e1 = b.x; e2 = b.y; e3 = b.z; e4 = b.w; }

        unsigned word = (i < 8) ? bits.x : (i < 16) ? bits.y : (i < 24) ? bits.z : bits.w;
        unsigned g = (word >> ((i & 7) * 4)) & 0xFu;
        unsigned incl = g;
        incl ^= incl << 1;
        incl ^= incl << 2;                          // inclusive prefix-XOR in the 4-group
        unsigned flipAll = (((baseAll ^ (pfx >> i)) & 1u) ? 0xFu : 0u);
        unsigned s = (incl ^ flipAll) & 0xFu;

        float a0 = fast_sqrt(fmaxf(e0 - e1, 0.0f));
        float a1 = fast_sqrt(fmaxf(e1 - e2, 0.0f));
        float a2 = fast_sqrt(fmaxf(e2 - e3, 0.0f));
        float a3 = fast_sqrt(fmaxf(e3 - e4, 0.0f));

        float4 o;
        o.x = apply_sign(a0,  s       & 1u);
        o.y = apply_sign(a1, (s >> 1) & 1u);
        o.z = apply_sign(a2, (s >> 2) & 1u);
        o.w = apply_sign(a3, (s >> 3) & 1u);
        out4[t >> 2] = o;
    }
}

// Block = (row, seg). 256 threads = 8 warps; warp span 4096 elems;
// lane owns 4 consecutive elems x 32 iters. flips read from HBM exactly once.
__global__ __launch_bounds__(256, 4)
void SignStickyPhaseReconstructor_kernel(const float* __restrict__ edc,
                                         const int*   __restrict__ flips,
                                         float*       __restrict__ out)
{
    const int N    = 131072;           // outputs per row (T-1)
    const int TROW = 131073;           // edc elements per row
    const int SEGN = N / SEGS;         // 32768 outputs per block

    const int row  = blockIdx.x >> 2;
    const int seg  = blockIdx.x & 3;
    const int lane = threadIdx.x & 31;
    const int w    = threadIdx.x >> 5;  // 0..7
    const unsigned lmask = (1u << lane) - 1u;

    const int4*  flips4 = (const int4*)(flips + row * N);
    float4*      out4   = (float4*)(out + row * N);
    const int rowBase   = row * TROW;
    const int o         = rowBase & 3;
    const int qbase     = (rowBase - o) >> 2;
    const float4* e4all = (const float4*)edc;

    const int warpBase = seg * SEGN + w * 4096;   // row-relative

    // ---------------- Pass 1: read flips once, build parity structure ----------------
    uint4 bits = make_uint4(0u, 0u, 0u, 0u);   // 128 flip bits per lane
    unsigned pfx = 0u;   // bit i = warp-local exclusive parity before this lane at iter i
    unsigned run = 0u;   // running warp parity

    #pragma unroll
    for (int i = 0; i < 32; i++) {
        const int t = warpBase + i * 128 + lane * 4;
        int4 fv = flips4[t >> 2];
        unsigned b0 = (unsigned)fv.x & 1u;
        unsigned b1 = (unsigned)fv.y & 1u;
        unsigned b2 = (unsigned)fv.z & 1u;
        unsigned b3 = (unsigned)fv.w & 1u;
        if (t == 0) b0 = 0u;                       // flips[:,0] is never applied
        unsigned g  = b0 | (b1 << 1) | (b2 << 2) | (b3 << 3);
        unsigned gp = b0 ^ b1 ^ b2 ^ b3;

        unsigned bal      = __ballot_sync(FULL_MASK, gp);
        unsigned laneExcl = (unsigned)__popc(bal & lmask) & 1u;
        pfx |= ((run ^ laneExcl) & 1u) << i;
        run ^= (unsigned)__popc(bal) & 1u;

        unsigned add = g << ((i & 7) * 4);
        if (i < 8)       bits.x |= add;
        else if (i < 16) bits.y |= add;
        else if (i < 24) bits.z |= add;
        else             bits.w |= add;
    }

    // ---------------- Block combine (8 warps) + lookback over <=3 predecessors ----------------
    __shared__ unsigned warpPar[8];
    __shared__ unsigned warpExcl[8];
    __shared__ unsigned sPrev;

    if (lane == 0) warpPar[w] = run;
    __syncthreads();
    if (w == 0) {
        unsigned p   = (lane < 8) ? warpPar[lane] : 0u;
        unsigned bal = __ballot_sync(FULL_MASK, p);
        if (lane < 8) warpExcl[lane] = (unsigned)__popc(bal & lmask) & 1u;
        if (lane == 0) {
            unsigned blockAgg = (unsigned)__popc(bal) & 1u;
            publish_flag(&g_flags[blockIdx.x], (int)(2u | blockAgg));
            unsigned prev = 0u;
            for (int pb = (int)blockIdx.x - seg; pb < (int)blockIdx.x; pb++) {
                int v;
                do { v = read_flag(&g_flags[pb]); } while (!(v & 2));
                prev ^= (unsigned)v & 1u;
            }
            sPrev = prev;
        }
    }
    __syncthreads();
    const unsigned baseAll = warpExcl[w] ^ sPrev;

    // ---------------- Pass 2: uniform dispatch on row misalignment ----------------
    switch (o) {
        case 0: pass2<0>(e4all, qbase, warpBase, lane, bits, pfx, baseAll, out4); break;
        case 1: pass2<1>(e4all, qbase, warpBase, lane, bits, pfx, baseAll, out4); break;
        case 2: pass2<2>(e4all, qbase, warpBase, lane, bits, pfx, baseAll, out4); break;
        default: pass2<3>(e4all, qbase, warpBase, lane, bits, pfx, baseAll, out4); break;
    }
}

extern "C" void kernel_launch(void* const* d_in, const int* in_sizes, int n_in,
                              void* d_out, int out_size)
{
    const int B = 256, T = 131073;

    const float* edc;
    const int*   flips;
    if (in_sizes[0] == B * T) {
        edc   = (const float*)d_in[0];
        flips = (const int*)  d_in[1];
    } else {
        edc   = (const float*)d_in[1];
        flips = (const int*)  d_in[0];
    }
    float* out = (float*)d_out;

    init_flags_kernel<<<1, NBLK>>>();
    SignStickyPhaseReconstructor_kernel<<<NBLK, 256>>>(edc, flips, out);
}

// round 5
// speedup vs baseline: 1.2091x; 1.2091x over previous
#include <cuda_runtime.h>
#include <cuda_bf16.h>
#include <cstdint>

#define FULL_MASK 0xFFFFFFFFu

#define NSTAGE     4
#define CHUNK      4096                    // output elems per chunk
#define NCHUNK     32                      // 131072 / 4096
#define FLIP_BYTES (CHUNK * 4)             // 16384
#define EDC_BYTES  (CHUNK * 4 + 16)        // 16400: covers 16B-align shift + boundary elem
#define STAGE_TX   (FLIP_BYTES + EDC_BYTES)

// dynamic smem layout (all offsets 16B-aligned)
#define OFF_MBAR   0                       // 4 x 8B mbarriers
#define OFF_WPAR   64                      // 32 x u32 warp parities
#define OFF_WEXCL  192                     // 32 x u32 exclusive scans
#define OFF_CARRY  320                     // 2 x u32 ping-pong carry
#define OFF_FLIPS  512
#define OFF_EDC    (OFF_FLIPS + NSTAGE * FLIP_BYTES)    // 66048
#define SMEM_BYTES (OFF_EDC + NSTAGE * EDC_BYTES)       // 131648

static __device__ __forceinline__ float fast_sqrt(float x) {
    float y; asm("sqrt.approx.f32 %0, %1;" : "=f"(y) : "f"(x)); return y;
}
static __device__ __forceinline__ float apply_sign(float a, unsigned neg) {
    return __uint_as_float(__float_as_uint(a) ^ (neg << 31));
}
static __device__ __forceinline__ void mbar_init(uint32_t mbar, uint32_t cnt) {
    asm volatile("mbarrier.init.shared.b64 [%0], %1;" :: "r"(mbar), "r"(cnt) : "memory");
}
static __device__ __forceinline__ void mbar_expect_tx(uint32_t mbar, uint32_t tx) {
    asm volatile("mbarrier.arrive.expect_tx.shared.b64 _, [%0], %1;" :: "r"(mbar), "r"(tx) : "memory");
}
static __device__ __forceinline__ void mbar_wait(uint32_t mbar, uint32_t phase) {
    uint32_t done;
    asm volatile("{\n\t.reg .pred p;\n\t"
                 "mbarrier.try_wait.parity.acquire.cta.shared::cta.b64 p, [%1], %2;\n\t"
                 "selp.b32 %0, 1, 0, p;\n\t}"
                 : "=r"(done) : "r"(mbar), "r"(phase) : "memory");
    if (!done) {
        asm volatile("{\n\t.reg .pred P1;\n\t"
                     "W_%=:\n\t"
                     "mbarrier.try_wait.parity.acquire.cta.shared::cta.b64 P1, [%0], %1, 0x989680;\n\t"
                     "@P1 bra.uni D_%=;\n\t"
                     "bra.uni W_%=;\n\t"
                     "D_%=:\n\t}"
                     :: "r"(mbar), "r"(phase) : "memory");
    }
}
static __device__ __forceinline__ void bulk_g2s(uint32_t dst, const void* src,
                                                uint32_t bytes, uint32_t mbar) {
    asm volatile("cp.async.bulk.shared::cluster.global.mbarrier::complete_tx::bytes "
                 "[%0], [%1], %2, [%3];"
                 :: "r"(dst), "l"(src), "r"(bytes), "r"(mbar) : "memory");
}

// Whole-row worker specialized on the row's 16B misalignment O = (row mod 4).
template <int O>
static __device__ __forceinline__ void run_row(char* sm, uint32_t sbase,
                                               const char* edcAligned,
                                               const char* flipsRow,
                                               float4* out4row,
                                               int tid, int lane, int w)
{
    const unsigned lmask = (1u << lane) - 1u;
    uint32_t* sWarpPar  = (uint32_t*)(sm + OFF_WPAR);
    uint32_t* sWarpExcl = (uint32_t*)(sm + OFF_WEXCL);
    uint32_t* sCarry    = (uint32_t*)(sm + OFF_CARRY);

    #pragma unroll 1
    for (int c = 0; c < NCHUNK; c++) {
        const int s        = c & (NSTAGE - 1);
        const uint32_t ph  = (unsigned)(c >> 2) & 1u;
        const uint32_t mb  = sbase + OFF_MBAR + s * 8;

        mbar_wait(mb, ph);                 // stage data (flips+edc) resident

        // ---- flips: parity structure for this thread's 4 elems ----
        const int4* fb = (const int4*)(sm + OFF_FLIPS + s * FLIP_BYTES);
        int4 fv = fb[tid];
        unsigned b0 = (unsigned)fv.x & 1u;
        unsigned b1 = (unsigned)fv.y & 1u;
        unsigned b2 = (unsigned)fv.z & 1u;
        unsigned b3 = (unsigned)fv.w & 1u;
        if (c == 0 && tid == 0) b0 = 0u;   // flips[:,0] never applied
        unsigned g  = b0 | (b1 << 1) | (b2 << 2) | (b3 << 3);
        unsigned gp = b0 ^ b1 ^ b2 ^ b3;

        unsigned bal      = __ballot_sync(FULL_MASK, gp);
        unsigned laneExcl = (unsigned)__popc(bal & lmask) & 1u;
        if (lane == 0) sWarpPar[w] = (unsigned)__popc(bal) & 1u;
        __syncthreads();
        if (w == 0) {
            unsigned p  = sWarpPar[lane];
            unsigned bw = __ballot_sync(FULL_MASK, p);
            sWarpExcl[lane] = (unsigned)__popc(bw & lmask) & 1u;
            if (lane == 0)
                sCarry[(c + 1) & 1] = sCarry[c & 1] ^ ((unsigned)__popc(bw) & 1u);
        }
        __syncthreads();
        const unsigned neg = (sCarry[c & 1] ^ sWarpExcl[w] ^ laneExcl) & 1u;

        unsigned incl = g;
        incl ^= incl << 1;
        incl ^= incl << 2;                 // inclusive prefix-XOR within the 4-group
        unsigned sgn = (incl ^ (neg ? 0xFu : 0u)) & 0xFu;

        // ---- edc: two aligned quads, static element select ----
        const float4* eb = (const float4*)(sm + OFF_EDC + s * EDC_BYTES);
        float4 qa = eb[tid];
        float4 qb = eb[tid + 1];
        float e0, e1, e2, e3, e4;
        if (O == 0)      { e0 = qa.x; e1 = qa.y; e2 = qa.z; e3 = qa.w; e4 = qb.x; }
        else if (O == 1) { e0 = qa.y; e1 = qa.z; e2 = qa.w; e3 = qb.x; e4 = qb.y; }
        else if (O == 2) { e0 = qa.z; e1 = qa.w; e2 = qb.x; e3 = qb.y; e4 = qb.z; }
        else             { e0 = qa.w; e1 = qb.x; e2 = qb.y; e3 = qb.z; e4 = qb.w; }

        float a0 = fast_sqrt(fmaxf(e0 - e1, 0.0f));
        float a1 = fast_sqrt(fmaxf(e1 - e2, 0.0f));
        float a2 = fast_sqrt(fmaxf(e2 - e3, 0.0f));
        float a3 = fast_sqrt(fmaxf(e3 - e4, 0.0f));

        float4 o;
        o.x = apply_sign(a0,  sgn       & 1u);
        o.y = apply_sign(a1, (sgn >> 1) & 1u);
        o.z = apply_sign(a2, (sgn >> 2) & 1u);
        o.w = apply_sign(a3, (sgn >> 3) & 1u);
        out4row[c * 1024 + tid] = o;

        __syncthreads();                   // stage fully consumed -> reusable
        if (tid == 0) {
            int n = c + NSTAGE;
            if (n < NCHUNK) {
                mbar_expect_tx(mb, STAGE_TX);
                bulk_g2s(sbase + OFF_FLIPS + s * FLIP_BYTES,
                         flipsRow + (size_t)n * FLIP_BYTES, FLIP_BYTES, mb);
                bulk_g2s(sbase + OFF_EDC + s * EDC_BYTES,
                         edcAligned + (size_t)n * (CHUNK * 4), EDC_BYTES, mb);
            }
        }
    }
}

// One block per row. 1024 threads; 4-stage cp.async.bulk pipeline keeps
// ~131KB/SM of loads in flight independent of register count.
__global__ __launch_bounds__(1024, 1)
void SignStickyPhaseReconstructor_kernel(const float* __restrict__ edc,
                                         const int*   __restrict__ flips,
                                         float*       __restrict__ out)
{
    extern __shared__ char sm[];
    const uint32_t sbase = (uint32_t)__cvta_generic_to_shared(sm);

    const int tid  = threadIdx.x;
    const int lane = tid & 31;
    const int w    = tid >> 5;
    const int row  = blockIdx.x;

    const char* edcRow = (const char*)(edc + (size_t)row * 131073);
    const uintptr_t ea = (uintptr_t)edcRow;
    const char* edcAligned = (const char*)(ea & ~(uintptr_t)15);
    const int o = (int)((ea & 15) >> 2);             // 0..3, uniform per block
    const char* flipsRow = (const char*)(flips + (size_t)row * 131072);
    float4* out4row = (float4*)(out + (size_t)row * 131072);

    if (tid == 0) {
        #pragma unroll
        for (int s = 0; s < NSTAGE; s++) mbar_init(sbase + OFF_MBAR + s * 8, 1);
        ((uint32_t*)(sm + OFF_CARRY))[0] = 0u;
        ((uint32_t*)(sm + OFF_CARRY))[1] = 0u;
    }
    __syncthreads();
    if (tid == 0) {
        asm volatile("fence.proxy.async.shared::cta;" ::: "memory");
        #pragma unroll
        for (int n = 0; n < NSTAGE; n++) {
            uint32_t mb = sbase + OFF_MBAR + n * 8;
            mbar_expect_tx(mb, STAGE_TX);
            bulk_g2s(sbase + OFF_FLIPS + n * FLIP_BYTES,
                     flipsRow + (size_t)n * FLIP_BYTES, FLIP_BYTES, mb);
            bulk_g2s(sbase + OFF_EDC + n * EDC_BYTES,
                     edcAligned + (size_t)n * (CHUNK * 4), EDC_BYTES, mb);
        }
    }

    switch (o) {
        case 0:  run_row<0>(sm, sbase, edcAligned, flipsRow, out4row, tid, lane, w); break;
        case 1:  run_row<1>(sm, sbase, edcAligned, flipsRow, out4row, tid, lane, w); break;
        case 2:  run_row<2>(sm, sbase, edcAligned, flipsRow, out4row, tid, lane, w); break;
        default: run_row<3>(sm, sbase, edcAligned, flipsRow, out4row, tid, lane, w); break;
    }
}

extern "C" void kernel_launch(void* const* d_in, const int* in_sizes, int n_in,
                              void* d_out, int out_size)
{
    const int B = 256, T = 131073;

    const float* edc;
    const int*   flips;
    if (in_sizes[0] == B * T) {
        edc   = (const float*)d_in[0];
        flips = (const int*)  d_in[1];
    } else {
        edc   = (const float*)d_in[1];
        flips = (const int*)  d_in[0];
    }
    float* out = (float*)d_out;

    cudaFuncSetAttribute(SignStickyPhaseReconstructor_kernel,
                         cudaFuncAttributeMaxDynamicSharedMemorySize, SMEM_BYTES);
    SignStickyPhaseReconstructor_kernel<<<B, 1024, SMEM_BYTES>>>(edc, flips, out);
}